// round 11
// baseline (speedup 1.0000x reference)
#include <cuda_runtime.h>

#define K 7
#define HH 1024
#define WW 1024
#define NBINS (K * K)
#define CHUNKS 16
#define NPROD (NBINS * CHUNKS)       // 784 producer blocks
#define TPB 128
#define NWARPS (TPB / 32)
#define NSLOT 32
#define SLOT_STRIDE 64               // 64 floats = 256B: distinct L2 lines/slices
#define QUOTA ((NPROD * NWARPS) / NSLOT)   // 3136/32 = 98 publishes per slot

// spread scratch (zero-init; consumer resets each run)
__device__ float        g_sum[NSLOT * SLOT_STRIDE];
__device__ unsigned int g_cnt[NSLOT * SLOT_STRIDE];

__device__ __forceinline__ void red_add_f32_relaxed(float* addr, float v) {
    asm volatile("red.relaxed.gpu.global.add.f32 [%0], %1;" :: "l"(addr), "f"(v) : "memory");
}
__device__ __forceinline__ void red_add_u32_release(unsigned int* addr, unsigned int v) {
    asm volatile("red.release.gpu.global.add.u32 [%0], %1;" :: "l"(addr), "r"(v) : "memory");
}
__device__ __forceinline__ unsigned int ld_acquire_u32(const unsigned int* addr) {
    unsigned int v;
    asm volatile("ld.acquire.gpu.global.u32 %0, [%1];" : "=r"(v) : "l"(addr) : "memory");
    return v;
}
__device__ __forceinline__ float ld_acquire_f32(const float* addr) {
    float v;
    asm volatile("ld.acquire.gpu.global.f32 %0, [%1];" : "=f"(v) : "l"(addr) : "memory");
    return v;
}

__device__ __forceinline__ void bin_extents(float ci, float cj, float h, float w,
                                            int bi, int bj,
                                            int& r0, int& r1, int& c0, int& c1) {
    // Mirror the reference float32 arithmetic.
    float i0 = ci - h * 0.5f, i1 = ci + h * 0.5f;
    float j0 = cj - w * 0.5f, j1 = cj + w * 0.5f;
    float stepi = (i1 - i0) / (float)(K + 1);
    float stepj = (j1 - j0) / (float)(K + 1);
    float ic = i0 + (float)(bi + 1) * stepi;
    float jc = j0 + (float)(bj + 1) * stepj;
    float bh2 = h / (float)K * 0.5f;
    float bw2 = w / (float)K * 0.5f;
    r0 = (int)floorf((ic - bh2) * (float)HH);
    r1 = (int)ceilf ((ic + bh2) * (float)HH);
    c0 = (int)floorf((jc - bw2) * (float)WW);
    c1 = (int)ceilf ((jc + bw2) * (float)WW);
    r0 = max(r0, 0); r1 = min(r1, HH);
    c0 = max(c0, 0); c1 = min(c1, WW);
}

__global__ __launch_bounds__(TPB)
void psroi_pc_kernel(const float* __restrict__ x,
                     const float* __restrict__ region,
                     float* __restrict__ out) {
    // -------- consumer: block 0, warp 0 spins concurrently (32 slots) -------
    if (blockIdx.x == 0) {
        if (threadIdx.x < 32) {
            const int lane = threadIdx.x;
            unsigned int* myc = &g_cnt[lane * SLOT_STRIDE];
            float*        mys = &g_sum[lane * SLOT_STRIDE];
            while (ld_acquire_u32(myc) < (unsigned)QUOTA) { /* spin */ }
            __syncwarp();
            float v = ld_acquire_f32(mys);
            // reset slots for next graph replay (ordered by kernel completion)
            *myc = 0u;
            *mys = 0.0f;
            #pragma unroll
            for (int o = 16; o > 0; o >>= 1)
                v += __shfl_down_sync(0xffffffffu, v, o);
            if (lane == 0) out[0] = v;
        }
        return;
    }

    // ---------------- producers: one (bin, chunk) each ----------------
    const int blk   = blockIdx.x - 1;     // 0..NPROD-1
    const int bin   = blk >> 4;           // /CHUNKS
    const int chunk = blk & (CHUNKS - 1);
    const int bi = bin / K, bj = bin % K;
    const int t    = threadIdx.x;
    const int wid  = t >> 5;
    const int lane = t & 31;

    const float4 reg = *reinterpret_cast<const float4*>(region);

    int r0, r1, c0, c1;
    bin_extents(reg.x, reg.y, reg.z, reg.w, bi, bj, r0, r1, c0, c1);

    const int total = (r1 - r0) * (c1 - c0);    // full-bin count (for scale)
    const int rpc   = (r1 - r0 + CHUNKS - 1) / CHUNKS;
    const int cr0   = r0 + chunk * rpc;
    const int cr1   = min(r1, cr0 + rpc);

    const float* __restrict__ chan = x + (size_t)bin * HH * WW;

    // warp-per-row, lane-per-column: coalesced, division-free, short chains
    float acc = 0.0f;
    for (int r = cr0 + wid; r < cr1; r += NWARPS) {
        const float* __restrict__ rowp = chan + (size_t)r * WW;
        for (int c = c0 + lane; c < c1; c += 32)
            acc += __ldg(rowp + c);
    }

    // warp-level reduce only; each warp publishes its own partial.
    #pragma unroll
    for (int o = 16; o > 0; o >>= 1)
        acc += __shfl_down_sync(0xffffffffu, acc, o);

    if (lane == 0) {
        const int slot = (blk * NWARPS + wid) & (NSLOT - 1);
        red_add_f32_relaxed(&g_sum[slot * SLOT_STRIDE],
                            acc / ((float)total * (float)NBINS));
        red_add_u32_release(&g_cnt[slot * SLOT_STRIDE], 1u);
    }
}

extern "C" void kernel_launch(void* const* d_in, const int* in_sizes, int n_in,
                              void* d_out, int out_size) {
    const float* x      = (const float*)d_in[0];
    const float* region = (const float*)d_in[1];
    float* out = (float*)d_out;

    psroi_pc_kernel<<<NPROD + 1, TPB>>>(x, region, out);
}

// round 12
// speedup vs baseline: 1.3413x; 1.3413x over previous
#include <cuda_runtime.h>

#define K 7
#define HH 1024
#define WW 1024
#define NBINS (K * K)
#define CHUNKS 16
#define NPROD (NBINS * CHUNKS)       // 784 producer blocks
#define TPB 128
#define NWARPS (TPB / 32)

// Single packed accumulator: bits[54:64) = arrival count, bits[0:54) = biased
// fixed-point sum (scale 2^44, per-publish bias 2^43). Zero-init; consumer
// resets each run. Integer adds => exactly deterministic.
__device__ unsigned long long g_acc;

#define COUNT_SHIFT 54
#define BIAS        (1ll << 43)
#define SCALE       0x1p44f
#define INV_SCALE   0x1p-44f
#define VALUE_MASK  ((1ull << COUNT_SHIFT) - 1ull)

__device__ __forceinline__ void red_add_u64_relaxed(unsigned long long* addr,
                                                    unsigned long long v) {
    asm volatile("red.relaxed.gpu.global.add.u64 [%0], %1;"
                 :: "l"(addr), "l"(v) : "memory");
}
__device__ __forceinline__ unsigned long long ld_relaxed_u64(const unsigned long long* addr) {
    unsigned long long v;
    asm volatile("ld.relaxed.gpu.global.u64 %0, [%1];" : "=l"(v) : "l"(addr) : "memory");
    return v;
}

__device__ __forceinline__ void bin_extents(float ci, float cj, float h, float w,
                                            int bi, int bj,
                                            int& r0, int& r1, int& c0, int& c1) {
    // Mirror the reference float32 arithmetic.
    float i0 = ci - h * 0.5f, i1 = ci + h * 0.5f;
    float j0 = cj - w * 0.5f, j1 = cj + w * 0.5f;
    float stepi = (i1 - i0) / (float)(K + 1);
    float stepj = (j1 - j0) / (float)(K + 1);
    float ic = i0 + (float)(bi + 1) * stepi;
    float jc = j0 + (float)(bj + 1) * stepj;
    float bh2 = h / (float)K * 0.5f;
    float bw2 = w / (float)K * 0.5f;
    r0 = (int)floorf((ic - bh2) * (float)HH);
    r1 = (int)ceilf ((ic + bh2) * (float)HH);
    c0 = (int)floorf((jc - bw2) * (float)WW);
    c1 = (int)ceilf ((jc + bw2) * (float)WW);
    r0 = max(r0, 0); r1 = min(r1, HH);
    c0 = max(c0, 0); c1 = min(c1, WW);
}

__global__ __launch_bounds__(TPB)
void psroi_pc_kernel(const float* __restrict__ x,
                     const float* __restrict__ region,
                     float* __restrict__ out) {
    // -------- consumer: block 0, single-word poll, single round trip --------
    if (blockIdx.x == 0) {
        if (threadIdx.x == 0) {
            unsigned long long w;
            do {
                w = ld_relaxed_u64(&g_acc);
            } while ((w >> COUNT_SHIFT) < (unsigned long long)NPROD);
            // value bits of the same atomic word are complete: no 2nd read.
            long long q = (long long)(w & VALUE_MASK)
                        - (long long)NPROD * BIAS;
            out[0] = (float)((double)q * (double)INV_SCALE);
            g_acc = 0ull;            // reset for next graph replay
        }
        return;
    }

    // ---------------- producers: one (bin, chunk) each ----------------
    const int blk   = blockIdx.x - 1;     // 0..NPROD-1
    const int bin   = blk >> 4;           // /CHUNKS
    const int chunk = blk & (CHUNKS - 1);
    const int bi = bin / K, bj = bin % K;
    const int t    = threadIdx.x;
    const int wid  = t >> 5;
    const int lane = t & 31;

    const float4 reg = *reinterpret_cast<const float4*>(region);

    int r0, r1, c0, c1;
    bin_extents(reg.x, reg.y, reg.z, reg.w, bi, bj, r0, r1, c0, c1);

    const int total = (r1 - r0) * (c1 - c0);    // full-bin count (for scale)
    const int rpc   = (r1 - r0 + CHUNKS - 1) / CHUNKS;
    const int cr0   = r0 + chunk * rpc;
    const int cr1   = min(r1, cr0 + rpc);

    const float* __restrict__ chan = x + (size_t)bin * HH * WW;

    // warp-per-row, lane-per-column: coalesced, division-free, short chains
    float acc = 0.0f;
    for (int r = cr0 + wid; r < cr1; r += NWARPS) {
        const float* __restrict__ rowp = chan + (size_t)r * WW;
        for (int c = c0 + lane; c < c1; c += 32)
            acc += __ldg(rowp + c);
    }

    // block reduce: warp shuffle, then thread 0 over 4 leaders
    #pragma unroll
    for (int o = 16; o > 0; o >>= 1)
        acc += __shfl_down_sync(0xffffffffu, acc, o);

    __shared__ float s[NWARPS];
    if (lane == 0) s[wid] = acc;
    __syncthreads();

    if (t == 0) {
        float v = s[0];
        #pragma unroll
        for (int i = 1; i < NWARPS; i++) v += s[i];
        v /= ((float)total * (float)NBINS);       // |v| < 1e-2
        // pack: count-unit + biased fixed-point value, single relaxed REDG
        long long q = __float2ll_rn(v * SCALE);
        unsigned long long w = (1ull << COUNT_SHIFT)
                             + (unsigned long long)(q + BIAS);
        red_add_u64_relaxed(&g_acc, w);
    }
}

extern "C" void kernel_launch(void* const* d_in, const int* in_sizes, int n_in,
                              void* d_out, int out_size) {
    const float* x      = (const float*)d_in[0];
    const float* region = (const float*)d_in[1];
    float* out = (float*)d_out;

    psroi_pc_kernel<<<NPROD + 1, TPB>>>(x, region, out);
}